// round 1
// baseline (speedup 1.0000x reference)
#include <cuda_runtime.h>

// LiveniumJoint: 6-step anchor-attraction iteration.
// Closed form: h stays in span{h0, a0n, a1n, a2n}; track coefficients
// (p, q0, q1, q2) with a scalar recurrence. One read of h0, one write of h.

#define DD 768
#define VV 192          // DD/4 float4 per row
#define KPL 6           // float4 per lane (192/32)
#define FULLMASK 0xffffffffu

__device__ float g_anch[3 * DD];  // normalized anchors
__device__ float g_G[9];          // Gram matrix of normalized anchors

// ---------------------------------------------------------------------------
// prep: normalize anchors, compute Gram. 1 block, 128 threads.
// ---------------------------------------------------------------------------
__global__ void liv_prep(const float* __restrict__ anchors) {
    __shared__ float s_an[3 * DD];
    int tid = threadIdx.x, w = tid >> 5, lane = tid & 31;
    if (w < 3) {
        float acc = 0.f;
        for (int k = lane; k < DD; k += 32) {
            float x = anchors[w * DD + k];
            acc = fmaf(x, x, acc);
        }
        #pragma unroll
        for (int o = 16; o; o >>= 1) acc += __shfl_xor_sync(FULLMASK, acc, o);
        float inv = 1.f / fmaxf(sqrtf(acc), 1e-12f);
        for (int k = lane; k < DD; k += 32) {
            float x = anchors[w * DD + k] * inv;
            s_an[w * DD + k] = x;
            g_anch[w * DD + k] = x;
        }
    }
    __syncthreads();
    if (w == 0) {
        float d00 = 0, d01 = 0, d02 = 0, d11 = 0, d12 = 0, d22 = 0;
        for (int k = lane; k < DD; k += 32) {
            float x0 = s_an[k], x1 = s_an[DD + k], x2 = s_an[2 * DD + k];
            d00 = fmaf(x0, x0, d00); d01 = fmaf(x0, x1, d01); d02 = fmaf(x0, x2, d02);
            d11 = fmaf(x1, x1, d11); d12 = fmaf(x1, x2, d12); d22 = fmaf(x2, x2, d22);
        }
        #pragma unroll
        for (int o = 16; o; o >>= 1) {
            d00 += __shfl_xor_sync(FULLMASK, d00, o);
            d01 += __shfl_xor_sync(FULLMASK, d01, o);
            d02 += __shfl_xor_sync(FULLMASK, d02, o);
            d11 += __shfl_xor_sync(FULLMASK, d11, o);
            d12 += __shfl_xor_sync(FULLMASK, d12, o);
            d22 += __shfl_xor_sync(FULLMASK, d22, o);
        }
        if (lane == 0) {
            g_G[0] = d00; g_G[1] = d01; g_G[2] = d02;
            g_G[3] = d01; g_G[4] = d11; g_G[5] = d12;
            g_G[6] = d02; g_G[7] = d12; g_G[8] = d22;
        }
    }
}

// ---------------------------------------------------------------------------
// main: warp per row, grid-stride with 1-deep prefetch pipeline.
// ---------------------------------------------------------------------------
__global__ __launch_bounds__(128, 3)
void liv_main(const float* __restrict__ h0,
              float* __restrict__ out_h,
              float* __restrict__ out_al,
              int B) {
    const int lane = threadIdx.x & 31;
    const int gw = (blockIdx.x * blockDim.x + threadIdx.x) >> 5;
    const int nw = (gridDim.x * blockDim.x) >> 5;

    // normalized anchors -> registers (coalesced, L2-hot)
    float4 A0[KPL], A1[KPL], A2[KPL];
    {
        const float4* av = (const float4*)g_anch;
        #pragma unroll
        for (int k = 0; k < KPL; k++) {
            A0[k] = av[k * 32 + lane];
            A1[k] = av[VV + k * 32 + lane];
            A2[k] = av[2 * VV + k * 32 + lane];
        }
    }
    const float G00 = g_G[0], G01 = g_G[1], G02 = g_G[2];
    const float G11 = g_G[4], G12 = g_G[5], G22 = g_G[8];

    int row = gw;
    if (row >= B) return;

    float4 h[KPL];
    {
        const float4* hp = (const float4*)h0 + (size_t)row * VV;
        #pragma unroll
        for (int k = 0; k < KPL; k++) h[k] = hp[k * 32 + lane];
    }

    while (row < B) {
        const int nrow = row + nw;

        // --- fused dots: N0=<h,h>, Tj=<h,anj> ---
        float N0 = 0.f, T0 = 0.f, T1 = 0.f, T2 = 0.f;
        #pragma unroll
        for (int k = 0; k < KPL; k++) {
            N0 = fmaf(h[k].x, h[k].x, N0);
            N0 = fmaf(h[k].y, h[k].y, N0);
            N0 = fmaf(h[k].z, h[k].z, N0);
            N0 = fmaf(h[k].w, h[k].w, N0);
            T0 = fmaf(h[k].x, A0[k].x, T0);
            T0 = fmaf(h[k].y, A0[k].y, T0);
            T0 = fmaf(h[k].z, A0[k].z, T0);
            T0 = fmaf(h[k].w, A0[k].w, T0);
            T1 = fmaf(h[k].x, A1[k].x, T1);
            T1 = fmaf(h[k].y, A1[k].y, T1);
            T1 = fmaf(h[k].z, A1[k].z, T1);
            T1 = fmaf(h[k].w, A1[k].w, T1);
            T2 = fmaf(h[k].x, A2[k].x, T2);
            T2 = fmaf(h[k].y, A2[k].y, T2);
            T2 = fmaf(h[k].z, A2[k].z, T2);
            T2 = fmaf(h[k].w, A2[k].w, T2);
        }

        // --- prefetch next row while scalar chain runs ---
        float4 hn[KPL];
        if (nrow < B) {
            const float4* hp = (const float4*)h0 + (size_t)nrow * VV;
            #pragma unroll
            for (int k = 0; k < KPL; k++) hn[k] = hp[k * 32 + lane];
        }

        #pragma unroll
        for (int o = 16; o; o >>= 1) {
            N0 += __shfl_xor_sync(FULLMASK, N0, o);
            T0 += __shfl_xor_sync(FULLMASK, T0, o);
            T1 += __shfl_xor_sync(FULLMASK, T1, o);
            T2 += __shfl_xor_sync(FULLMASK, T2, o);
        }

        // --- scalar recurrence: h = p*h0 + q·a_n (all lanes, redundant) ---
        float p = 1.f, q0 = 0.f, q1 = 0.f, q2 = 0.f;
        float al0 = 0.f, al1 = 0.f, al2 = 0.f;
        #pragma unroll
        for (int s = 0; s < 7; s++) {
            float s0 = fmaf(p, T0, fmaf(q0, G00, fmaf(q1, G01, q2 * G02)));
            float s1 = fmaf(p, T1, fmaf(q0, G01, fmaf(q1, G11, q2 * G12)));
            float s2 = fmaf(p, T2, fmaf(q0, G02, fmaf(q1, G12, q2 * G22)));
            float qT = fmaf(q0, T0, fmaf(q1, T1, q2 * T2));
            float n2 = fmaf(p, fmaf(p, N0, qT),
                            fmaf(q0, s0, fmaf(q1, s1, q2 * s2)));
            float n = sqrtf(n2);
            float inv = 1.f / fmaxf(n, 1e-12f);
            al0 = s0 * inv; al1 = s1 * inv; al2 = s2 * inv;
            if (s == 6) break;  // 7th pass = final alignments only

            // softmax(beta * alignments), beta = 20
            float l0 = 20.f * al0, l1 = 20.f * al1, l2 = 20.f * al2;
            float m = fmaxf(l0, fmaxf(l1, l2));
            float e0 = expf(l0 - m), e1 = expf(l1 - m), e2 = expf(l2 - m);
            float invW = 1.f / (e0 + e1 + e2);
            float w0 = e0 * invW, w1 = e1 * invW, w2 = e2 * invW;

            float c = fmaf(w0, al0, fmaf(w1, al1, w2 * al2));  // <h_n, target>
            float beta = fmaf(-0.05f, c, 1.f);                  // 1 - alpha*c
            float delta = 0.05f * n;                            // alpha*||h||
            p *= beta;
            q0 = fmaf(beta, q0, delta * w0);
            q1 = fmaf(beta, q1, delta * w1);
            q2 = fmaf(beta, q2, delta * w2);

            // clip: ||h_new||^2 = n2 * (1 + alpha^2*(||t||^2 - c^2))
            float t2 = fmaf(w0 * w0, G00,
                       fmaf(w1 * w1, G11,
                       fmaf(w2 * w2, G22,
                       2.f * fmaf(w0 * w1, G01,
                             fmaf(w0 * w2, G02, w1 * w2 * G12)))));
            float n2b = n2 * fmaf(0.0025f, t2 - c * c, 1.f);
            float nb = sqrtf(n2b);
            if (nb > 10.f) {
                float g = 10.f / (nb + 1e-8f);
                p *= g; q0 *= g; q1 *= g; q2 *= g;
            }
        }

        // --- output: h_out = p*h0 + q0*a0 + q1*a1 + q2*a2 ---
        float4* op = (float4*)out_h + (size_t)row * VV;
        #pragma unroll
        for (int k = 0; k < KPL; k++) {
            float4 o;
            o.x = fmaf(p, h[k].x, fmaf(q0, A0[k].x, fmaf(q1, A1[k].x, q2 * A2[k].x)));
            o.y = fmaf(p, h[k].y, fmaf(q0, A0[k].y, fmaf(q1, A1[k].y, q2 * A2[k].y)));
            o.z = fmaf(p, h[k].z, fmaf(q0, A0[k].z, fmaf(q1, A1[k].z, q2 * A2[k].z)));
            o.w = fmaf(p, h[k].w, fmaf(q0, A0[k].w, fmaf(q1, A1[k].w, q2 * A2[k].w)));
            op[k * 32 + lane] = o;
        }
        if (lane < 3) {
            float v = (lane == 0) ? al0 : ((lane == 1) ? al1 : al2);
            out_al[(size_t)row * 3 + lane] = v;
        }

        #pragma unroll
        for (int k = 0; k < KPL; k++) h[k] = hn[k];
        row = nrow;
    }
}

// ---------------------------------------------------------------------------
extern "C" void kernel_launch(void* const* d_in, const int* in_sizes, int n_in,
                              void* d_out, int out_size) {
    const float* h0 = (const float*)d_in[0];       // [B, 768]
    const float* anchors = (const float*)d_in[1];  // [3, 768]
    const int B = in_sizes[0] / DD;

    float* out_h = (float*)d_out;                  // [B, 768]
    float* out_al = (float*)d_out + (size_t)B * DD;  // [B, 3]

    liv_prep<<<1, 128>>>(anchors);

    const int threads = 128;                 // 4 warps/block
    int blocks = 2048;                       // ~8 rows per warp
    int total_warps = blocks * (threads / 32);
    if (total_warps > B) blocks = (B + 3) / 4;
    liv_main<<<blocks, threads>>>(h0, out_h, out_al, B);
}